// round 1
// baseline (speedup 1.0000x reference)
#include <cuda_runtime.h>
#include <math.h>

#define NEGV (-1e30f)

// per-batch loss scratch (no cudaMalloc allowed)
__device__ float g_loss[4096];

// ---------------------------------------------------------------------------
// Kernel 1: log_tm[t, b, c] = log(y_pred[b, t, c])   (transpose + log, fused)
// ---------------------------------------------------------------------------
__global__ void log_transpose_kernel(const float* __restrict__ p,
                                     float* __restrict__ out,
                                     int T, int B, int C, long long total) {
    long long idx = (long long)blockIdx.x * blockDim.x + threadIdx.x;
    if (idx >= total) return;
    int c = (int)(idx % C);
    long long r = idx / C;
    int b = (int)(r % B);
    int t = (int)(r / B);
    out[idx] = __logf(p[((long long)b * T + t) * C + c]);
}

// ---------------------------------------------------------------------------
// Kernel 2: CTC forward recursion. One block per batch element.
//   alpha_new[s] = lse(alpha[s], alpha[s-1], alpha[s-2]*skip_ok) + logp[t, ext[s]]
// Alpha freezes at t >= input_length, so we just stop the loop there.
// ---------------------------------------------------------------------------
__global__ void ctc_forward_kernel(const float* __restrict__ logp, // [T,B,C] (== d_out)
                                   const int* __restrict__ labels, // [B,L]
                                   const int* __restrict__ in_len, // [B]
                                   const int* __restrict__ lab_len,// [B]
                                   int T, int B, int C, int L) {
    extern __shared__ float smem[];
    const int S = 2 * L + 1;
    float* alphaA = smem;            // S floats
    float* alphaB = alphaA + S;      // S floats
    float* row    = alphaB + S;      // C floats (current time's log-probs for this b)
    int*   lab    = (int*)(row + C); // L ints

    const int b   = blockIdx.x;
    const int tid = threadIdx.x;
    const int BD  = blockDim.x;

    for (int j = tid; j < L; j += BD) lab[j] = labels[b * L + j];
    __syncthreads();

    int il = in_len[b];  il = il < 1 ? 1 : (il > T ? T : il);
    int ll = lab_len[b]; ll = ll < 1 ? 1 : (ll > L ? L : ll);

    // Per-thread state metadata (S=513, BD=256 -> at most 3 states/thread)
    int   extc[8];
    char  skipok[8];
    int   ns = 0;
    for (int s = tid; s < S; s += BD) {
        if (s & 1) {
            int j = (s - 1) >> 1;
            extc[ns]   = lab[j];
            skipok[ns] = (char)((j > 0) && (lab[j] != lab[j - 1]));
        } else {
            extc[ns]   = 0;      // blank
            skipok[ns] = 0;
        }
        ns++;
    }

    // ---- t = 0 ----
    {
        const float* g0 = logp + (long long)b * C;  // t=0 row
        for (int c = tid; c < C; c += BD) row[c] = g0[c];
        __syncthreads();
        int i = 0;
        for (int s = tid; s < S; s += BD, ++i)
            alphaA[s] = (s < 2) ? row[extc[i]] : NEGV;
        __syncthreads();
    }

    float* cur = alphaA;
    float* nxt = alphaB;

    // ---- t = 1 .. il-1 ----
    for (int t = 1; t < il; ++t) {
        const float* g = logp + ((long long)t * B + b) * C;
        for (int c = tid; c < C; c += BD) row[c] = g[c];
        __syncthreads();  // row ready; prev iter's readers done

        int i = 0;
        for (int s = tid; s < S; s += BD, ++i) {
            float a0 = cur[s];
            float a1 = (s >= 1) ? cur[s - 1] : NEGV;
            float a2 = skipok[i] ? cur[s - 2] : NEGV;  // skipok implies s>=3
            float m  = fmaxf(a0, fmaxf(a1, a2));
            float sum = __expf(a0 - m) + __expf(a1 - m) + __expf(a2 - m);
            nxt[s] = m + __logf(sum) + row[extc[i]];
        }
        __syncthreads();
        float* tmp = cur; cur = nxt; nxt = tmp;
    }

    if (tid == 0) {
        float e1 = cur[2 * ll - 1];
        float e2 = cur[2 * ll];
        float m  = fmaxf(e1, e2);
        g_loss[b] = -(m + __logf(__expf(e1 - m) + __expf(e2 - m)));
    }
}

// ---------------------------------------------------------------------------
// Kernel 3: mean over batch -> out[loss_idx]
// ---------------------------------------------------------------------------
__global__ void mean_loss_kernel(float* __restrict__ out, int B, long long loss_idx) {
    float s = 0.f;
    for (int i = threadIdx.x; i < B; i += 32) s += g_loss[i];
    #pragma unroll
    for (int o = 16; o; o >>= 1) s += __shfl_down_sync(0xffffffffu, s, o);
    if (threadIdx.x == 0) out[loss_idx] = s / (float)B;
}

// ---------------------------------------------------------------------------
extern "C" void kernel_launch(void* const* d_in, const int* in_sizes, int n_in,
                              void* d_out, int out_size) {
    const int*   y_true = (const int*)  d_in[0];  // [B, L]
    const float* y_pred = (const float*)d_in[1];  // [B, T, C]
    const int*   il     = (const int*)  d_in[2];  // [B]
    const int*   ll     = (const int*)  d_in[3];  // [B]

    const int B = in_sizes[2];
    const int L = in_sizes[0] / B;
    const int C = 128;                       // fixed for this problem
    const int T = in_sizes[1] / (B * C);
    float* out = (float*)d_out;

    const long long total = (long long)T * B * C;

    // 1) log + transpose into out[0 .. T*B*C)
    {
        int threads = 256;
        long long blocks = (total + threads - 1) / threads;
        log_transpose_kernel<<<(unsigned)blocks, threads>>>(y_pred, out, T, B, C, total);
    }

    // 2) CTC forward (reads the log_tm we just wrote)
    {
        const int S = 2 * L + 1;
        size_t smem = (size_t)(2 * S + C) * sizeof(float) + (size_t)L * sizeof(int);
        ctc_forward_kernel<<<B, 256, smem>>>(out, y_true, il, ll, T, B, C, L);
    }

    // 3) mean loss -> out[out_size - 1]
    mean_loss_kernel<<<1, 32>>>(out, B, (long long)out_size - 1);
}

// round 2
// speedup vs baseline: 1.0646x; 1.0646x over previous
#include <cuda_runtime.h>
#include <math.h>

#define NEGV (-1e30f)

// per-batch loss scratch (no cudaMalloc allowed)
__device__ float g_loss[4096];

// ---------------------------------------------------------------------------
// Fused kernel:
//   blocks [0, ctcBlocks)           : CTC forward recursion, one block per batch
//   blocks [ctcBlocks, gridDim.x)   : log + transpose  out[t,b,c] = log(p[b,t,c])
// The two parts are independent (CTC computes its own logs from y_pred).
// ---------------------------------------------------------------------------
__global__ void ctc_fused_kernel(const float* __restrict__ p,      // [B,T,C]
                                 const int* __restrict__ labels,   // [B,L]
                                 const int* __restrict__ in_len,   // [B]
                                 const int* __restrict__ lab_len,  // [B]
                                 float* __restrict__ out,          // [T,B,C] (+loss)
                                 int T, int B, int C, int L,
                                 int ctcBlocks) {
    if ((int)blockIdx.x >= ctcBlocks) {
        // ---------------- log + transpose (vectorized float4) ----------------
        const int c4w = C >> 2;                       // float4 per row
        const long long total4 = (long long)T * B * c4w;
        const float4* __restrict__ p4 = (const float4*)p;
        float4* __restrict__ o4 = (float4*)out;
        const long long stride = (long long)(gridDim.x - ctcBlocks) * blockDim.x;
        for (long long v = (long long)(blockIdx.x - ctcBlocks) * blockDim.x + threadIdx.x;
             v < total4; v += stride) {
            int c4 = (int)(v % c4w);
            long long rr = v / c4w;           // rr = t*B + b
            int b = (int)(rr % B);
            long long t = rr / B;
            float4 x = p4[((long long)b * T + t) * c4w + c4];
            float4 y;
            y.x = __logf(x.x); y.y = __logf(x.y);
            y.z = __logf(x.z); y.w = __logf(x.w);
            o4[v] = y;
        }
        return;
    }

    // -------------------------- CTC forward ---------------------------------
    extern __shared__ float smem[];
    const int S = 2 * L + 1;
    float* alphaA = smem;              // S
    float* alphaB = alphaA + S;        // S
    float* buf0   = alphaB + S;        // C   (row double-buffer)
    float* buf1   = buf0 + C;          // C
    int*   lab    = (int*)(buf1 + C);  // L

    const int b   = blockIdx.x;
    const int tid = threadIdx.x;
    const int BD  = blockDim.x;

    for (int j = tid; j < L; j += BD) lab[j] = labels[b * L + j];
    __syncthreads();

    int il = in_len[b];  il = il < 1 ? 1 : (il > T ? T : il);
    int ll = lab_len[b]; ll = ll < 1 ? 1 : (ll > L ? L : ll);

    // Per-thread state metadata (S=513, BD=256 -> <=3 states/thread)
    int  extc[3];
    bool skipok[3];
    int  ns = 0;
    for (int s = tid; s < S; s += BD) {
        if (s & 1) {
            int j = (s - 1) >> 1;
            extc[ns]   = lab[j];
            skipok[ns] = (j > 0) && (lab[j] != lab[j - 1]);
        } else {
            extc[ns]   = 0;     // blank
            skipok[ns] = false;
        }
        ns++;
    }

    const float* __restrict__ pb = p + (long long)b * T * C;

    // ---- t = 0: stage row 0; prefetch row 1 ----
    float r = 1.0f;  // prefetch register (raw prob, logged at store time)
    if (tid < C) {
        buf0[tid] = __logf(pb[tid]);
        if (1 < il) r = pb[C + tid];   // issue LDG for t=1 early
    }
    __syncthreads();
    {
        int i = 0;
        for (int s = tid; s < S; s += BD, ++i)
            alphaA[s] = (s < 2) ? buf0[extc[i]] : NEGV;
    }
    // no barrier needed here: t=1 stores into buf1 (disjoint from buf0) and its
    // own barrier orders alphaA writes before the t=1 compute reads.

    float* cur = alphaA;
    float* nxt = alphaB;

    // ---- t = 1 .. il-1 : single barrier per step, prefetched row ----
    for (int t = 1; t < il; ++t) {
        float* rowbuf = (t & 1) ? buf1 : buf0;
        if (tid < C) {
            rowbuf[tid] = __logf(r);                       // store staged row t
            if (t + 1 < il) r = pb[(long long)(t + 1) * C + tid]; // prefetch t+1
        }
        __syncthreads();   // rowbuf ready; prev step's alpha writes visible

        int i = 0;
        #pragma unroll 3
        for (int s = tid; s < S; s += BD, ++i) {
            float a0 = cur[s];
            float a1 = (s >= 1) ? cur[s - 1] : NEGV;
            float a2 = skipok[i] ? cur[s - 2] : NEGV;
            float m  = fmaxf(a0, fmaxf(a1, a2));
            float sum = __expf(a0 - m) + __expf(a1 - m) + __expf(a2 - m);
            nxt[s] = m + __logf(sum) + rowbuf[extc[i]];
        }
        float* tmp = cur; cur = nxt; nxt = tmp;
    }

    __syncthreads();
    if (tid == 0) {
        float e1 = cur[2 * ll - 1];
        float e2 = cur[2 * ll];
        float m  = fmaxf(e1, e2);
        g_loss[b] = -(m + __logf(__expf(e1 - m) + __expf(e2 - m)));
    }
}

// ---------------------------------------------------------------------------
// Mean over batch -> out[loss_idx]
// ---------------------------------------------------------------------------
__global__ void mean_loss_kernel(float* __restrict__ out, int B, long long loss_idx) {
    float s = 0.f;
    for (int i = threadIdx.x; i < B; i += 32) s += g_loss[i];
    #pragma unroll
    for (int o = 16; o; o >>= 1) s += __shfl_down_sync(0xffffffffu, s, o);
    if (threadIdx.x == 0) out[loss_idx] = s / (float)B;
}

// ---------------------------------------------------------------------------
extern "C" void kernel_launch(void* const* d_in, const int* in_sizes, int n_in,
                              void* d_out, int out_size) {
    const int*   y_true = (const int*)  d_in[0];  // [B, L]
    const float* y_pred = (const float*)d_in[1];  // [B, T, C]
    const int*   il     = (const int*)  d_in[2];  // [B]
    const int*   ll     = (const int*)  d_in[3];  // [B]

    const int B = in_sizes[2];
    const int L = in_sizes[0] / B;
    const int C = 128;                       // fixed for this problem
    const int T = in_sizes[1] / (B * C);
    float* out = (float*)d_out;

    const int ctcBlocks   = B;               // one block per batch element
    const int transBlocks = 1408;            // fills remaining SMs for transpose
    const int S = 2 * L + 1;
    size_t smem = (size_t)(2 * S + 2 * C) * sizeof(float) + (size_t)L * sizeof(int);

    ctc_fused_kernel<<<ctcBlocks + transBlocks, 256, smem>>>(
        y_pred, y_true, il, ll, out, T, B, C, L, ctcBlocks);

    mean_loss_kernel<<<1, 32>>>(out, B, (long long)out_size - 1);
}

// round 3
// speedup vs baseline: 2.8505x; 2.6775x over previous
#include <cuda_runtime.h>
#include <math.h>

#define NEGV (-1e30f)
#define LN2F 0.6931471805599453f

// scratch (no cudaMalloc allowed)
__device__ float g_loss[4096];
__device__ unsigned int g_ctr;   // wraps back to 0 every launch via atomicInc

__device__ __forceinline__ unsigned int smem_u32(const void* p) {
    unsigned int a;
    asm("{ .reg .u64 t; cvta.to.shared.u64 t, %1; cvt.u32.u64 %0, t; }"
        : "=r"(a) : "l"(p));
    return a;
}
__device__ __forceinline__ void cp_async16(unsigned int dst, const void* src) {
    asm volatile("cp.async.cg.shared.global [%0], [%1], 16;\n" :: "r"(dst), "l"(src));
}
__device__ __forceinline__ void cp_commit() {
    asm volatile("cp.async.commit_group;\n" ::: "memory");
}
__device__ __forceinline__ void cp_wait6() {
    asm volatile("cp.async.wait_group 6;\n" ::: "memory");
}

// ---------------------------------------------------------------------------
// Fused kernel:
//   blocks [0, ctcBlocks)         : CTC forward, one block per batch element
//   blocks [ctcBlocks, gridDim.x) : log + transpose  out[t,b,c] = log(p[b,t,c])
// ---------------------------------------------------------------------------
__global__ void __launch_bounds__(256)
ctc_fused_kernel(const float* __restrict__ p,      // [B,T,C]
                 const int* __restrict__ labels,   // [B,L]
                 const int* __restrict__ in_len,   // [B]
                 const int* __restrict__ lab_len,  // [B]
                 float* __restrict__ out,          // [T,B,C] (+ loss at end)
                 int T, int B, int C, int L,
                 int ctcBlocks, long long loss_idx) {
    if ((int)blockIdx.x >= ctcBlocks) {
        // ---------------- log + transpose (float4) --------------------------
        const int c4w = C >> 2;
        const long long total4 = (long long)T * B * c4w;
        const float4* __restrict__ p4 = (const float4*)p;
        float4* __restrict__ o4 = (float4*)out;
        const long long stride = (long long)(gridDim.x - ctcBlocks) * blockDim.x;
        for (long long v = (long long)(blockIdx.x - ctcBlocks) * blockDim.x + threadIdx.x;
             v < total4; v += stride) {
            int c4 = (int)(v % c4w);
            long long rr = v / c4w;          // rr = t*B + b
            int b = (int)(rr % B);
            long long t = rr / B;
            float4 x = p4[((long long)b * T + t) * c4w + c4];
            float4 y;
            y.x = __logf(x.x); y.y = __logf(x.y);
            y.z = __logf(x.z); y.w = __logf(x.w);
            o4[v] = y;
        }
        return;
    }

    // -------------------------- CTC forward (log2 domain) -------------------
    // Thread tid owns states 2tid (blank/even) and 2tid+1 (label/odd).
    // Last thread additionally owns state 2L (final blank).
    extern __shared__ float smem[];
    float* ring = smem;              // 8 * C floats (cp.async row ring)
    float* bnd  = ring + 8 * C;      // 2 * 8 floats (cross-warp odd boundary, parity-buffered)

    const int b    = blockIdx.x;
    const int tid  = threadIdx.x;
    const int w    = tid >> 5;
    const int lane = tid & 31;
    const int last = blockDim.x - 1;

    int il = in_len[b];  il = il < 1 ? 1 : (il > T ? T : il);
    int ll = lab_len[b]; ll = ll < 1 ? 1 : (ll > L ? L : ll);

    const int lab  = labels[b * L + tid];
    const bool skip = (tid > 0) && (lab != labels[b * L + tid - 1]);

    const float* __restrict__ pb = p + (long long)b * T * C;
    const unsigned int ring_u = smem_u32(ring);

    // prologue: rows 0..6 in flight (group g carries row g)
    if (w == 0) {
        for (int k = 0; k < 7; ++k) {
            if (k < il)
                cp_async16(ring_u + (unsigned)(((k & 7) * C + lane * 4) * 4),
                           pb + (long long)k * C + lane * 4);
            cp_commit();
        }
    }

    float ae, ao, a5 = NEGV;

    // ---- t = 0 ----
    if (w == 0) cp_wait6();
    __syncthreads();
    {
        const float* row = ring;     // slot 0
        float lpb = __log2f(row[0]);
        float lpl = __log2f(row[lab]);
        ae = (tid == 0) ? lpb : NEGV;
        ao = (tid == 0) ? lpl : NEGV;
        if (w == 0) {
            if (7 < il)
                cp_async16(ring_u + (unsigned)(((7 & 7) * C + lane * 4) * 4),
                           pb + (long long)7 * C + lane * 4);
            cp_commit();
        }
        if (lane == 31) bnd[8 + w] = ao;    // parity (t+1)&1 = 1
    }

    // ---- t = 1 .. il-1 ----
    for (int t = 1; t < il; ++t) {
        if (w == 0) cp_wait6();             // row t's group complete
        __syncthreads();                    // row visible; slot (t+7)&7 free; bnd[t&1] ready

        const float* row = ring + (t & 7) * C;
        float lpb = __log2f(row[0]);
        float lpl = __log2f(row[lab]);

        float a_ol = __shfl_up_sync(0xffffffffu, ao, 1);   // old odd of left neighbor
        if (lane == 0) a_ol = (w > 0) ? bnd[(t & 1) * 8 + (w - 1)] : NEGV;

        // even state 2tid: lse(old_even, old_odd_left)
        float me = fmaxf(ae, a_ol);
        float de = fminf(ae, a_ol) - me;
        float ve = me + __log2f(1.0f + exp2f(de));

        // odd state 2tid+1: lse(old_odd, old_even, skip ? old_odd_left)
        float a2 = skip ? a_ol : NEGV;
        float mo = fmaxf(ao, fmaxf(ae, a2));
        float so = exp2f(ao - mo) + exp2f(ae - mo) + exp2f(a2 - mo);
        float vo = mo + __log2f(so);

        // state 2L (last blank): lse(old_2L, own old_odd)
        if (tid == last) {
            float m5 = fmaxf(a5, ao);
            float d5 = fminf(a5, ao) - m5;
            a5 = m5 + __log2f(1.0f + exp2f(d5)) + lpb;
        }

        ae = ve + lpb;
        ao = vo + lpl;

        if (w == 0) {                       // keep group count aligned: always commit
            if (t + 7 < il)
                cp_async16(ring_u + (unsigned)((((t + 7) & 7) * C + lane * 4) * 4),
                           pb + (long long)(t + 7) * C + lane * 4);
            cp_commit();
        }
        if (lane == 31) bnd[((t + 1) & 1) * 8 + w] = ao;
    }

    // ---- finalize: dump alpha, compute loss, fused mean via atomic counter --
    __syncthreads();
    float* sA = ring;                       // reuse ring (all transfers consumed)
    sA[2 * tid]     = ae;
    sA[2 * tid + 1] = ao;
    if (tid == last) sA[2 * blockDim.x] = a5;
    __syncthreads();

    if (tid == 0) {
        float e1 = sA[2 * ll - 1];
        float e2 = sA[2 * ll];
        float m  = fmaxf(e1, e2);
        float l2 = m + __log2f(exp2f(e1 - m) + exp2f(e2 - m));
        g_loss[b] = -l2 * LN2F;
        __threadfence();
        unsigned int old = atomicInc(&g_ctr, (unsigned)(B - 1));   // wraps to 0
        if (old == (unsigned)(B - 1)) {
            __threadfence();
            volatile float* gl = g_loss;
            float s = 0.f;
            for (int i = 0; i < B; ++i) s += gl[i];
            out[loss_idx] = s / (float)B;
        }
    }
}

// ---------------------------------------------------------------------------
extern "C" void kernel_launch(void* const* d_in, const int* in_sizes, int n_in,
                              void* d_out, int out_size) {
    const int*   y_true = (const int*)  d_in[0];  // [B, L]
    const float* y_pred = (const float*)d_in[1];  // [B, T, C]
    const int*   il     = (const int*)  d_in[2];  // [B]
    const int*   ll     = (const int*)  d_in[3];  // [B]

    const int B = in_sizes[2];
    const int L = in_sizes[0] / B;                // 256
    const int C = 128;                            // fixed for this problem
    const int T = in_sizes[1] / (B * C);
    float* out = (float*)d_out;

    const int ctcBlocks   = B;                    // one block per batch element
    const int transBlocks = 1408;                 // fill remaining SMs
    size_t smem = (size_t)(8 * C + 16) * sizeof(float);

    ctc_fused_kernel<<<ctcBlocks + transBlocks, L, smem>>>(
        y_pred, y_true, il, ll, out, T, B, C, L,
        ctcBlocks, (long long)out_size - 1);
}

// round 6
// speedup vs baseline: 3.2979x; 1.1570x over previous
#include <cuda_runtime.h>
#include <math.h>

#define NEGV (-1e30f)
#define LN2F 0.6931471805599453f
#define DPRE 8

// scratch (no cudaMalloc allowed)
__device__ float g_loss[4096];
__device__ unsigned int g_ctr;   // wraps back to 0 every launch via atomicInc

__device__ __forceinline__ float ex2(float x) {
    float r; asm("ex2.approx.f32 %0, %1;" : "=f"(r) : "f"(x)); return r;
}
__device__ __forceinline__ float lg2(float x) {
    float r; asm("lg2.approx.f32 %0, %1;" : "=f"(r) : "f"(x)); return r;
}

// ---------------------------------------------------------------------------
// Fused kernel:
//   blocks [0, ctcBlocks)         : CTC forward (log2 domain, 1 barrier/step)
//   blocks [ctcBlocks, gridDim.x) : log + transpose  out[t,b,c] = log(p[b,t,c])
// ---------------------------------------------------------------------------
__global__ void __launch_bounds__(256)
ctc_fused_kernel(const float* __restrict__ p,      // [B,T,C]
                 const int* __restrict__ labels,   // [B,L]
                 const int* __restrict__ in_len,   // [B]
                 const int* __restrict__ lab_len,  // [B]
                 float* __restrict__ out,          // [T,B,C] (+ loss at end)
                 int T, int B, int C, int L,
                 int ctcBlocks, long long loss_idx) {
    if ((int)blockIdx.x >= ctcBlocks) {
        // ---------------- log + transpose (float4) --------------------------
        const int c4w = C >> 2;
        const long long total4 = (long long)T * B * c4w;
        const float4* __restrict__ p4 = (const float4*)p;
        float4* __restrict__ o4 = (float4*)out;
        const long long stride = (long long)(gridDim.x - ctcBlocks) * blockDim.x;
        for (long long v = (long long)(blockIdx.x - ctcBlocks) * blockDim.x + threadIdx.x;
             v < total4; v += stride) {
            int c4 = (int)(v % c4w);
            long long rr = v / c4w;          // rr = t*B + b
            int b = (int)(rr % B);
            long long t = rr / B;
            float4 x = p4[((long long)b * T + t) * c4w + c4];
            float4 y;
            y.x = __logf(x.x); y.y = __logf(x.y);
            y.z = __logf(x.z); y.w = __logf(x.w);
            o4[v] = y;
        }
        return;
    }

    // ---------------- CTC forward, log2 domain, register alphas -------------
    // Thread tid owns states 2tid (blank/even) and 2tid+1 (label/odd);
    // the last thread additionally owns state 2L (final blank).
    // Cross-warp boundary (lane31 odd alpha) via parity-buffered smem,
    // one __syncthreads per timestep (R3-proven pattern).
    __shared__ float bnd[2][8];
    __shared__ float sA[513];

    const int b    = blockIdx.x;
    const int tid  = threadIdx.x;
    const int w    = tid >> 5;
    const int lane = tid & 31;
    const int last = blockDim.x - 1;

    int il = in_len[b];  il = il < 1 ? 1 : (il > T ? T : il);
    int ll = lab_len[b]; ll = ll < 1 ? 1 : (ll > L ? L : ll);

    const int  lab  = labels[b * L + tid];
    const bool skip = (tid > 0) && (lab != labels[b * L + tid - 1]);

    const float* __restrict__ pbase = p + (long long)b * T * C;   // blank col 0
    const float* __restrict__ plabp = pbase + lab;

    // ---- t = 0 ----
    float ae, ao, a5 = NEGV;
    {
        float pb0 = __ldg(pbase);
        float pl0 = __ldg(plabp);
        ae = (tid == 0) ? lg2(pb0) : NEGV;
        ao = (tid == 0) ? lg2(pl0) : NEGV;
        if (lane == 31) bnd[1][w] = ao;      // parity for t=1
    }

    // prefetch rows 1..DPRE (per-thread: 2 scalars per row)
    float rpb[DPRE], rpl[DPRE];
    #pragma unroll
    for (int j = 0; j < DPRE; ++j) {
        int tt = 1 + j; if (tt > il - 1) tt = il - 1;
        rpb[j] = __ldg(pbase + (long long)tt * C);
        rpl[j] = __ldg(plabp + (long long)tt * C);
    }
    __syncthreads();

    // ---- t = 1 .. il-1 (il uniform per block) ----
    for (int tb = 1; tb < il; tb += DPRE) {
        #pragma unroll
        for (int j = 0; j < DPRE; ++j) {
            int t = tb + j;
            if (t >= il) break;              // uniform across block

            float pb = rpb[j];
            float pl = rpl[j];

            // neighbor's old odd alpha (state 2tid-1)
            float a_ol = __shfl_up_sync(0xffffffffu, ao, 1);
            if (lane == 0) a_ol = (w > 0) ? bnd[t & 1][w - 1] : NEGV;

            // even state 2tid: lse2(ae, a_ol), prob folded into lg2
            float me = fmaxf(ae, a_ol);
            float ve = me + lg2((1.0f + ex2(fminf(ae, a_ol) - me)) * pb);

            // odd state 2tid+1: lse3(ao, ae, skip ? a_ol), prob folded
            float a2 = skip ? a_ol : NEGV;
            float mo = fmaxf(ao, fmaxf(ae, a2));
            float so = ex2(ao - mo) + ex2(ae - mo) + ex2(a2 - mo);
            float vo = mo + lg2(so * pl);

            // state 2L (final blank), uses OLD ao
            if (tid == last) {
                float m5 = fmaxf(a5, ao);
                a5 = m5 + lg2((1.0f + ex2(fminf(a5, ao) - m5)) * pb);
            }
            ae = ve;
            ao = vo;

            if (lane == 31) bnd[(t + 1) & 1][w] = ao;

            // prefetch row t + DPRE into this slot
            int tp = t + DPRE; if (tp > il - 1) tp = il - 1;
            rpb[j] = __ldg(pbase + (long long)tp * C);
            rpl[j] = __ldg(plabp + (long long)tp * C);

            __syncthreads();
        }
    }

    // ---- finalize: dump alpha, loss, fused mean via atomic counter ---------
    sA[2 * tid]     = ae;
    sA[2 * tid + 1] = ao;
    if (tid == last) sA[512] = a5;
    __syncthreads();

    if (tid == 0) {
        float e1 = sA[2 * ll - 1];
        float e2 = sA[2 * ll];
        float m  = fmaxf(e1, e2);
        float l2 = m + lg2(ex2(e1 - m) + ex2(e2 - m));
        g_loss[b] = -l2 * LN2F;
        __threadfence();
        unsigned int old = atomicInc(&g_ctr, (unsigned)(B - 1));   // wraps to 0
        if (old == (unsigned)(B - 1)) {
            __threadfence();
            volatile float* gl = g_loss;
            float s = 0.f;
            for (int i = 0; i < B; ++i) s += gl[i];
            out[loss_idx] = s / (float)B;
        }
    }
}

// ---------------------------------------------------------------------------
extern "C" void kernel_launch(void* const* d_in, const int* in_sizes, int n_in,
                              void* d_out, int out_size) {
    const int*   y_true = (const int*)  d_in[0];  // [B, L]
    const float* y_pred = (const float*)d_in[1];  // [B, T, C]
    const int*   il     = (const int*)  d_in[2];  // [B]
    const int*   ll     = (const int*)  d_in[3];  // [B]

    const int B = in_sizes[2];
    const int L = in_sizes[0] / B;                // 256
    const int C = 128;                            // fixed for this problem
    const int T = in_sizes[1] / (B * C);
    float* out = (float*)d_out;

    const int ctcBlocks   = B;                    // one block per batch element
    const int transBlocks = 1408;                 // fill remaining SMs

    ctc_fused_kernel<<<ctcBlocks + transBlocks, L>>>(
        y_pred, y_true, il, ll, out, T, B, C, L,
        ctcBlocks, (long long)out_size - 1);
}